// round 12
// baseline (speedup 1.0000x reference)
#include <cuda_runtime.h>
#include <cstdint>

// GraphAttention: nf=x@W ; g=head-sum(nf) ; s1/s2=g.a1/a2 ; lrelu+mask+softmax(j) ; agg.
// R8 tiling; x read directly from gmem (broadcast LDG) + L2 prefetch; attn in own buffer.
#define NN      16
#define FINN    64
#define COLS    128
#define ROWS_PP 64
#define NPASS   8192
#define GRID    2048
#define THREADS 256

// smem offsets (floats)
#define OFF_W   0            // [64 k][128 c]
#define OFF_NF  8192         // [64 r][132]
#define OFF_AT  16640        // attn [i*68 + j*4 + h]
#define OFF_S1  20992        // [64][4]
#define OFF_S2  21248
#define OFF_A1  21504        // [4][36]
#define OFF_A2  21648
#define SMEM_FLOATS 21792
#define SMEM_BYTES  (SMEM_FLOATS * 4)   // 87168 B -> 2 blocks/SM

typedef unsigned long long ull;

__device__ __forceinline__ ull pack2(float lo, float hi) {
    ull o; asm("mov.b64 %0, {%1, %2};" : "=l"(o) : "f"(lo), "f"(hi)); return o;
}
__device__ __forceinline__ void fma2(ull& d, ull a, ull b, ull c) {
    asm("fma.rn.f32x2 %0, %1, %2, %3;" : "=l"(d) : "l"(a), "l"(b), "l"(c));
}

__global__ __launch_bounds__(THREADS, 2)
void gat_kernel(const float* __restrict__ x,
                const float* __restrict__ W,
                const float* __restrict__ attv,
                const float* __restrict__ adj,
                float* __restrict__ out)
{
    extern __shared__ float smf[];
    const int t = threadIdx.x;
    const int warp = t >> 5;
    const int lane = t & 31;
    const int c4 = lane;                  // col group c4*4..+3; warp covers all 128 cols
    const int hh = c4 >> 3;

    // ---- one-time setup: W, att vectors, adjacency bitmask ----
    #pragma unroll
    for (int q = 0; q < 8; q++)
        ((float4*)(smf + OFF_W))[t + 256 * q] = ((const float4*)W)[t + 256 * q];
    {
        const int h = t >> 6, f2 = t & 63;
        const float v = attv[t];
        if (f2 < 32) smf[OFF_A1 + h * 36 + f2] = v;
        else         smf[OFF_A2 + h * 36 + (f2 - 32)] = v;
    }
    unsigned amask = 0;
    {
        const int i = (t >> 2) & 15;
        #pragma unroll
        for (int j = 0; j < NN; j++)
            if (adj[i * NN + j] != 0.f) amask |= (1u << j);
    }
    __syncthreads();

    for (int tp = blockIdx.x; tp < NPASS; tp += GRID) {
        const size_t row0 = (size_t)tp * ROWS_PP;

        // ---- GEMM: warp -> rows 8w..8w+7, lane -> 4 cols; x via broadcast LDG ----
        {
            const float* xg = x + (row0 + 8 * warp) * FINN;   // warp-uniform
            const float* wcol = smf + OFF_W + c4 * 4;
            ull acc[8][2];
            #pragma unroll
            for (int r = 0; r < 8; r++) { acc[r][0] = 0; acc[r][1] = 0; }
            #pragma unroll
            for (int k4 = 0; k4 < 16; k4++) {
                const ulonglong2 w0 = *(const ulonglong2*)(wcol + (k4 * 4 + 0) * COLS);
                const ulonglong2 w1 = *(const ulonglong2*)(wcol + (k4 * 4 + 1) * COLS);
                const ulonglong2 w2 = *(const ulonglong2*)(wcol + (k4 * 4 + 2) * COLS);
                const ulonglong2 w3 = *(const ulonglong2*)(wcol + (k4 * 4 + 3) * COLS);
                #pragma unroll
                for (int r = 0; r < 8; r++) {
                    const float4 xv = __ldg((const float4*)(xg + r * FINN + k4 * 4));
                    ull xx;
                    xx = pack2(xv.x, xv.x);
                    fma2(acc[r][0], xx, w0.x, acc[r][0]); fma2(acc[r][1], xx, w0.y, acc[r][1]);
                    xx = pack2(xv.y, xv.y);
                    fma2(acc[r][0], xx, w1.x, acc[r][0]); fma2(acc[r][1], xx, w1.y, acc[r][1]);
                    xx = pack2(xv.z, xv.z);
                    fma2(acc[r][0], xx, w2.x, acc[r][0]); fma2(acc[r][1], xx, w2.y, acc[r][1]);
                    xx = pack2(xv.w, xv.w);
                    fma2(acc[r][0], xx, w3.x, acc[r][0]); fma2(acc[r][1], xx, w3.y, acc[r][1]);
                }
            }
            #pragma unroll
            for (int r = 0; r < 8; r++) {
                ulonglong2 st; st.x = acc[r][0]; st.y = acc[r][1];
                *(ulonglong2*)(smf + OFF_NF + (8 * warp + r) * 132 + c4 * 4) = st;
            }
        }
        __syncthreads();

        // ---- s1/s2: thread -> (row = t>>2, fq = t&3 -> 8 f's); shfl-reduce over fq ----
        {
            const int row = t >> 2, fq = t & 3;
            const int fb = fq * 8;
            const float* nfr = smf + OFF_NF + row * 132 + fb;
            float g[8];
            #pragma unroll
            for (int b4 = 0; b4 < 2; b4++) {
                float4 s = *(const float4*)(nfr + b4 * 4);
                const float4 n1 = *(const float4*)(nfr + 32 + b4 * 4);
                const float4 n2 = *(const float4*)(nfr + 64 + b4 * 4);
                const float4 n3 = *(const float4*)(nfr + 96 + b4 * 4);
                s.x += n1.x + n2.x + n3.x; s.y += n1.y + n2.y + n3.y;
                s.z += n1.z + n2.z + n3.z; s.w += n1.w + n2.w + n3.w;
                g[b4 * 4 + 0] = s.x; g[b4 * 4 + 1] = s.y; g[b4 * 4 + 2] = s.z; g[b4 * 4 + 3] = s.w;
            }
            float p1[4], p2[4];
            #pragma unroll
            for (int h = 0; h < 4; h++) {
                const float4 a1a = *(const float4*)(smf + OFF_A1 + h * 36 + fb);
                const float4 a1b = *(const float4*)(smf + OFF_A1 + h * 36 + fb + 4);
                const float4 a2a = *(const float4*)(smf + OFF_A2 + h * 36 + fb);
                const float4 a2b = *(const float4*)(smf + OFF_A2 + h * 36 + fb + 4);
                p1[h] = g[0] * a1a.x + g[1] * a1a.y + g[2] * a1a.z + g[3] * a1a.w
                      + g[4] * a1b.x + g[5] * a1b.y + g[6] * a1b.z + g[7] * a1b.w;
                p2[h] = g[0] * a2a.x + g[1] * a2a.y + g[2] * a2a.z + g[3] * a2a.w
                      + g[4] * a2b.x + g[5] * a2b.y + g[6] * a2b.z + g[7] * a2b.w;
            }
            #pragma unroll
            for (int h = 0; h < 4; h++) {
                p1[h] += __shfl_xor_sync(0xFFFFFFFF, p1[h], 1);
                p1[h] += __shfl_xor_sync(0xFFFFFFFF, p1[h], 2);
                p2[h] += __shfl_xor_sync(0xFFFFFFFF, p2[h], 1);
                p2[h] += __shfl_xor_sync(0xFFFFFFFF, p2[h], 2);
            }
            if (fq == 0) {
                *(float4*)(smf + OFF_S1 + row * 4) = make_float4(p1[0], p1[1], p1[2], p1[3]);
                *(float4*)(smf + OFF_S2 + row * 4) = make_float4(p2[0], p2[1], p2[2], p2[3]);
            }
        }
        // graph = 16 rows = warp pair
        asm volatile("bar.sync %0, 64;" :: "r"(1 + (warp >> 1)) : "memory");

        // ---- softmax: thread -> (i = t>>2, h = t&3); attn -> [i*68 + j*4 + h] ----
        {
            const int i = t >> 2, h = t & 3;
            const int jb = i & ~15;
            const float s1 = smf[OFF_S1 + i * 4 + h];
            float sc[NN];
            float mx = -1e30f;
            #pragma unroll
            for (int j = 0; j < NN; j++) {
                float s = s1 + smf[OFF_S2 + (jb + j) * 4 + h];
                s = (s > 0.f) ? s : 0.2f * s;
                const bool valid = (amask >> j) & 1u;
                sc[j] = valid ? s : -1e30f;
                mx = (valid && s > mx) ? s : mx;
            }
            float sum = 0.f;
            #pragma unroll
            for (int j = 0; j < NN; j++) {
                const float e = (sc[j] > -1e29f) ? __expf(sc[j] - mx) : 0.f;
                sc[j] = e;
                sum += e;
            }
            const float inv = 1.f / sum;
            #pragma unroll
            for (int j = 0; j < NN; j++)
                smf[OFF_AT + i * 68 + j * 4 + h] = sc[j] * inv;
        }
        __syncwarp();   // agg warp w reads attn rows 8w..8w+7 = written by this warp

        // ---- L2 prefetch of next pass's x (16KB: one 64B line per thread) ----
        if (tp + GRID < NPASS) {
            const char* pf = (const char*)(x + (row0 + (size_t)GRID * ROWS_PP) * FINN) + t * 64;
            asm volatile("prefetch.global.L2 [%0];" :: "l"(pf));
        }

        // ---- agg: warp -> 8 i-rows, lane -> c4; j register-blocked by 4 ----
        {
            const int ar0 = 8 * warp;
            const int ajb = (warp >> 1) * 16;
            ull acc[8][2];
            #pragma unroll
            for (int r = 0; r < 8; r++) { acc[r][0] = 0; acc[r][1] = 0; }
            #pragma unroll
            for (int j4 = 0; j4 < 4; j4++) {
                ull nfv[4][2];
                #pragma unroll
                for (int jj = 0; jj < 4; jj++) {
                    const ulonglong2 v = *(const ulonglong2*)(smf + OFF_NF + (ajb + 4 * j4 + jj) * 132 + c4 * 4);
                    nfv[jj][0] = v.x; nfv[jj][1] = v.y;
                }
                #pragma unroll
                for (int r = 0; r < 8; r++) {
                    const float* ap = smf + OFF_AT + (ar0 + r) * 68 + hh;
                    ull aa;
                    float a;
                    a = ap[(4 * j4 + 0) * 4]; aa = pack2(a, a);
                    fma2(acc[r][0], aa, nfv[0][0], acc[r][0]); fma2(acc[r][1], aa, nfv[0][1], acc[r][1]);
                    a = ap[(4 * j4 + 1) * 4]; aa = pack2(a, a);
                    fma2(acc[r][0], aa, nfv[1][0], acc[r][0]); fma2(acc[r][1], aa, nfv[1][1], acc[r][1]);
                    a = ap[(4 * j4 + 2) * 4]; aa = pack2(a, a);
                    fma2(acc[r][0], aa, nfv[2][0], acc[r][0]); fma2(acc[r][1], aa, nfv[2][1], acc[r][1]);
                    a = ap[(4 * j4 + 3) * 4]; aa = pack2(a, a);
                    fma2(acc[r][0], aa, nfv[3][0], acc[r][0]); fma2(acc[r][1], aa, nfv[3][1], acc[r][1]);
                }
            }
            #pragma unroll
            for (int r = 0; r < 8; r++) {
                ulonglong2 st; st.x = acc[r][0]; st.y = acc[r][1];
                *(ulonglong2*)(out + (row0 + ar0 + r) * COLS + c4 * 4) = st;
            }
        }
        __syncthreads();   // nf/attn dead before next pass overwrites
    }
}

extern "C" void kernel_launch(void* const* d_in, const int* in_sizes, int n_in,
                              void* d_out, int out_size) {
    const float* x    = (const float*)d_in[0];
    const float* W    = (const float*)d_in[1];
    const float* attv = (const float*)d_in[2];
    const float* adj  = (const float*)d_in[3];
    float* out = (float*)d_out;
    (void)in_sizes; (void)n_in; (void)out_size;

    cudaFuncSetAttribute(gat_kernel, cudaFuncAttributeMaxDynamicSharedMemorySize, SMEM_BYTES);
    gat_kernel<<<GRID, THREADS, SMEM_BYTES>>>(x, W, attv, adj, out);
}

// round 13
// speedup vs baseline: 1.6879x; 1.6879x over previous
#include <cuda_runtime.h>
#include <cstdint>

// GraphAttention: nf=x@W ; g=head-sum(nf) ; s1/s2=g.a1/a2 ; lrelu+mask+softmax(j) ; agg.
// Fully warp-pair-local pipeline: graph = 16 rows = 1 warp pair; no block-wide syncs in loop.
#define NN      16
#define FINN    64
#define COLS    128
#define ROWS_PP 64
#define NPASS   8192
#define GRID    2048
#define THREADS 256

// smem offsets (floats)
#define OFF_W   0            // [64 k][128 c]
#define OFF_NF  8192         // [64 r][132]
#define OFF_XA  16640        // x [r][68] / attn [i*68 + h*16 + j] (pair-local time-disjoint alias)
#define OFF_S1  20992        // [64][4]
#define OFF_S2  21248
#define OFF_A1  21504        // [4][36]
#define OFF_A2  21648
#define SMEM_FLOATS 21792
#define SMEM_BYTES  (SMEM_FLOATS * 4)   // 87168 B -> 2 blocks/SM

typedef unsigned long long ull;

__device__ __forceinline__ ull pack2(float lo, float hi) {
    ull o; asm("mov.b64 %0, {%1, %2};" : "=l"(o) : "f"(lo), "f"(hi)); return o;
}
__device__ __forceinline__ void fma2(ull& d, ull a, ull b, ull c) {
    asm("fma.rn.f32x2 %0, %1, %2, %3;" : "=l"(d) : "l"(a), "l"(b), "l"(c));
}

__global__ __launch_bounds__(THREADS, 2)
void gat_kernel(const float* __restrict__ x,
                const float* __restrict__ W,
                const float* __restrict__ attv,
                const float* __restrict__ adj,
                float* __restrict__ out)
{
    extern __shared__ float smf[];
    const int t = threadIdx.x;
    const int warp = t >> 5;
    const int lane = t & 31;
    const int pt   = t & 63;              // thread index within pair
    const int p    = warp >> 1;           // pair = graph slot (0..3)
    const int R0   = 16 * p;              // pair's local row base
    const int bid  = p + 1;               // named barrier id for this pair

    // GEMM mapping: warp -> (pair, col half); lane -> (row half, col4)
    const int CB   = (warp & 1) * 64;
    const int c4p  = lane & 15;
    const int rh   = lane >> 4;
    // agg mapping: warp -> 8 i-rows of own graph; lane -> c4; head = lane>>3
    const int ar0  = R0 + 8 * (warp & 1);
    const int hh   = lane >> 3;

    // ---- one-time setup: W, att vectors, adjacency bitmask ----
    #pragma unroll
    for (int q = 0; q < 8; q++)
        ((float4*)(smf + OFF_W))[t + 256 * q] = ((const float4*)W)[t + 256 * q];
    {
        const int h = t >> 6, f2 = t & 63;
        const float v = attv[t];
        if (f2 < 32) smf[OFF_A1 + h * 36 + f2] = v;
        else         smf[OFF_A2 + h * 36 + (f2 - 32)] = v;
    }
    unsigned amask = 0;
    {
        const int i = (pt >> 2);
        #pragma unroll
        for (int j = 0; j < NN; j++)
            if (adj[i * NN + j] != 0.f) amask |= (1u << j);
    }
    __syncthreads();

    for (int tp = blockIdx.x; tp < NPASS; tp += GRID) {
        const size_t row0 = (size_t)tp * ROWS_PP;

        // ---- stage x: pair loads its own graph (16x64), pitch-68 ----
        {
            const float4* gx = (const float4*)(x + (row0 + R0) * FINN);
            #pragma unroll
            for (int q = 0; q < 4; q++) {
                const int idx = pt + 64 * q;
                const float4 v = gx[idx];
                *(float4*)(smf + OFF_XA + (R0 + (idx >> 4)) * 68 + 4 * (idx & 15)) = v;
            }
        }
        asm volatile("bar.sync %0, 64;" :: "r"(bid) : "memory");

        // ---- GEMM: warp = 16 rows x 64 cols; lane = 8 rows x 4 cols ----
        {
            const float* xrow = smf + OFF_XA + (R0 + 8 * rh) * 68;
            const float* wcol = smf + OFF_W + CB + c4p * 4;
            ull acc[8][2];
            #pragma unroll
            for (int r = 0; r < 8; r++) { acc[r][0] = 0; acc[r][1] = 0; }
            #pragma unroll
            for (int k4 = 0; k4 < 16; k4++) {
                float4 xv[8];
                #pragma unroll
                for (int r = 0; r < 8; r++)
                    xv[r] = *(const float4*)(xrow + r * 68 + k4 * 4);
                #pragma unroll
                for (int kk = 0; kk < 4; kk++) {
                    const ulonglong2 wv = *(const ulonglong2*)(wcol + (k4 * 4 + kk) * COLS);
                    #pragma unroll
                    for (int r = 0; r < 8; r++) {
                        const float xs = (kk == 0) ? xv[r].x : (kk == 1) ? xv[r].y
                                       : (kk == 2) ? xv[r].z : xv[r].w;
                        const ull xx = pack2(xs, xs);
                        fma2(acc[r][0], xx, wv.x, acc[r][0]);
                        fma2(acc[r][1], xx, wv.y, acc[r][1]);
                    }
                }
            }
            #pragma unroll
            for (int r = 0; r < 8; r++) {
                ulonglong2 st; st.x = acc[r][0]; st.y = acc[r][1];
                *(ulonglong2*)(smf + OFF_NF + (R0 + 8 * rh + r) * 132 + CB + c4p * 4) = st;
            }
        }
        asm volatile("bar.sync %0, 64;" :: "r"(bid) : "memory");

        // ---- s1/s2: thread -> (row = R0 + pt>>2, fq = pt&3 -> 8 f's); shfl-reduce over fq ----
        {
            const int row = R0 + (pt >> 2), fq = pt & 3;
            const int fb = fq * 8;
            const float* nfr = smf + OFF_NF + row * 132 + fb;
            float g[8];
            #pragma unroll
            for (int b4 = 0; b4 < 2; b4++) {
                float4 s = *(const float4*)(nfr + b4 * 4);
                const float4 n1 = *(const float4*)(nfr + 32 + b4 * 4);
                const float4 n2 = *(const float4*)(nfr + 64 + b4 * 4);
                const float4 n3 = *(const float4*)(nfr + 96 + b4 * 4);
                s.x += n1.x + n2.x + n3.x; s.y += n1.y + n2.y + n3.y;
                s.z += n1.z + n2.z + n3.z; s.w += n1.w + n2.w + n3.w;
                g[b4 * 4 + 0] = s.x; g[b4 * 4 + 1] = s.y; g[b4 * 4 + 2] = s.z; g[b4 * 4 + 3] = s.w;
            }
            float p1[4], p2[4];
            #pragma unroll
            for (int h = 0; h < 4; h++) {
                const float4 a1a = *(const float4*)(smf + OFF_A1 + h * 36 + fb);
                const float4 a1b = *(const float4*)(smf + OFF_A1 + h * 36 + fb + 4);
                const float4 a2a = *(const float4*)(smf + OFF_A2 + h * 36 + fb);
                const float4 a2b = *(const float4*)(smf + OFF_A2 + h * 36 + fb + 4);
                p1[h] = g[0] * a1a.x + g[1] * a1a.y + g[2] * a1a.z + g[3] * a1a.w
                      + g[4] * a1b.x + g[5] * a1b.y + g[6] * a1b.z + g[7] * a1b.w;
                p2[h] = g[0] * a2a.x + g[1] * a2a.y + g[2] * a2a.z + g[3] * a2a.w
                      + g[4] * a2b.x + g[5] * a2b.y + g[6] * a2b.z + g[7] * a2b.w;
            }
            #pragma unroll
            for (int h = 0; h < 4; h++) {
                p1[h] += __shfl_xor_sync(0xFFFFFFFF, p1[h], 1);
                p1[h] += __shfl_xor_sync(0xFFFFFFFF, p1[h], 2);
                p2[h] += __shfl_xor_sync(0xFFFFFFFF, p2[h], 1);
                p2[h] += __shfl_xor_sync(0xFFFFFFFF, p2[h], 2);
            }
            if (fq == 0) {
                *(float4*)(smf + OFF_S1 + row * 4) = make_float4(p1[0], p1[1], p1[2], p1[3]);
                *(float4*)(smf + OFF_S2 + row * 4) = make_float4(p2[0], p2[1], p2[2], p2[3]);
            }
        }
        asm volatile("bar.sync %0, 64;" :: "r"(bid) : "memory");

        // ---- softmax: thread -> (i = R0 + pt>>2, h = pt&3); attn -> [i*68 + h*16 + j] ----
        {
            const int i = R0 + (pt >> 2), h = pt & 3;
            const float s1 = smf[OFF_S1 + i * 4 + h];
            float sc[NN];
            float mx = -1e30f;
            #pragma unroll
            for (int j = 0; j < NN; j++) {
                float s = s1 + smf[OFF_S2 + (R0 + j) * 4 + h];
                s = (s > 0.f) ? s : 0.2f * s;
                const bool valid = (amask >> j) & 1u;
                sc[j] = valid ? s : -1e30f;
                mx = (valid && s > mx) ? s : mx;
            }
            float sum = 0.f;
            #pragma unroll
            for (int j = 0; j < NN; j++) {
                const float e = (sc[j] > -1e29f) ? __expf(sc[j] - mx) : 0.f;
                sc[j] = e;
                sum += e;
            }
            const float inv = 1.f / sum;
            float* arow = smf + OFF_XA + i * 68 + h * 16;
            #pragma unroll
            for (int j4 = 0; j4 < 4; j4++)
                *(float4*)(arow + 4 * j4) = make_float4(sc[4 * j4] * inv, sc[4 * j4 + 1] * inv,
                                                        sc[4 * j4 + 2] * inv, sc[4 * j4 + 3] * inv);
        }
        __syncwarp();   // agg warp reads attn rows written by this warp's softmax threads

        // ---- agg: warp -> 8 i-rows, lane -> c4 (4 cols); j register-blocked by 4 ----
        {
            ull acc[8][2];
            #pragma unroll
            for (int r = 0; r < 8; r++) { acc[r][0] = 0; acc[r][1] = 0; }
            #pragma unroll
            for (int j4 = 0; j4 < 4; j4++) {
                ull nfv[4][2];
                #pragma unroll
                for (int jj = 0; jj < 4; jj++) {
                    const ulonglong2 v = *(const ulonglong2*)(smf + OFF_NF + (R0 + 4 * j4 + jj) * 132 + lane * 4);
                    nfv[jj][0] = v.x; nfv[jj][1] = v.y;
                }
                #pragma unroll
                for (int r = 0; r < 8; r++) {
                    const float4 af = *(const float4*)(smf + OFF_XA + (ar0 + r) * 68 + hh * 16 + 4 * j4);
                    ull aa;
                    aa = pack2(af.x, af.x);
                    fma2(acc[r][0], aa, nfv[0][0], acc[r][0]); fma2(acc[r][1], aa, nfv[0][1], acc[r][1]);
                    aa = pack2(af.y, af.y);
                    fma2(acc[r][0], aa, nfv[1][0], acc[r][0]); fma2(acc[r][1], aa, nfv[1][1], acc[r][1]);
                    aa = pack2(af.z, af.z);
                    fma2(acc[r][0], aa, nfv[2][0], acc[r][0]); fma2(acc[r][1], aa, nfv[2][1], acc[r][1]);
                    aa = pack2(af.w, af.w);
                    fma2(acc[r][0], aa, nfv[3][0], acc[r][0]); fma2(acc[r][1], aa, nfv[3][1], acc[r][1]);
                }
            }
            #pragma unroll
            for (int r = 0; r < 8; r++) {
                ulonglong2 st; st.x = acc[r][0]; st.y = acc[r][1];
                *(ulonglong2*)(out + (row0 + ar0 + r) * COLS + lane * 4) = st;
            }
        }
        // end of pass: next stage overwrites x/attn, next GEMM overwrites nf (pair-local)
        asm volatile("bar.sync %0, 64;" :: "r"(bid) : "memory");
    }
}

extern "C" void kernel_launch(void* const* d_in, const int* in_sizes, int n_in,
                              void* d_out, int out_size) {
    const float* x    = (const float*)d_in[0];
    const float* W    = (const float*)d_in[1];
    const float* attv = (const float*)d_in[2];
    const float* adj  = (const float*)d_in[3];
    float* out = (float*)d_out;
    (void)in_sizes; (void)n_in; (void)out_size;

    cudaFuncSetAttribute(gat_kernel, cudaFuncAttributeMaxDynamicSharedMemorySize, SMEM_BYTES);
    gat_kernel<<<GRID, THREADS, SMEM_BYTES>>>(x, W, attv, adj, out);
}